// round 12
// baseline (speedup 1.0000x reference)
#include <cuda_runtime.h>
#include <cstdint>

// Problem constants
#define NBATCH 64
#define NBINS  256
#define ELEMS_PER_BATCH (256*32*32)          // 262144 floats per batch per tensor
#define F4_PER_BATCH    (ELEMS_PER_BATCH/4)  // 65536 float4
#define CHUNKS 2                             // blocks per (batch, tensor)
#define F4_PER_CHUNK (F4_PER_BATCH/CHUNKS)   // 32768 float4 per block
#define HIST_THREADS 512
#define NWARPS 16
#define ATOMIC_WARPS 11                      // warps on the ATOMS pipe
#define F4_PER_WARP (F4_PER_CHUNK/NWARPS)    // 2048 float4 per warp
#define WARP_ITERS (F4_PER_WARP/32)          // 64 iterations
#define BLOCKS_PER_BATCH (2*CHUNKS)          // 4 (both tensors)

// Scratch (no device allocation allowed).
__device__ unsigned int g_part[2][NBATCH][CHUNKS][NBINS];
__device__ float        g_kl[NBATCH];
__device__ unsigned int g_bctr[NBATCH];      // per-batch tickets (reset by winner)
__device__ unsigned int g_ctr;               // global ticket (reset by final block)

// Exact float->small-int: for integer-valued f in [0,255], low byte of
// bits(f + 2^23) is the integer. Avoids the F2I conversion pipe.
__device__ __forceinline__ unsigned int bin_of(float f) {
    return __float_as_uint(f + 8388608.0f);   // low 8 bits = (int)f
}

// ---------------------------------------------------------------------------
// Single fused kernel. grid = (CHUNKS, NBATCH, 2) = 256 blocks, block = 512.
// Warps 0..10: smem-atomic histogram (bank-exclusive sh[bin][lane]).
// Warps 11..15: bit-slice ballot counting — ZERO smem-port ops; lane L owns
// bins [8L, 8L+8) in registers; merged with 8 atomics at the end.
// The two paths run concurrently on different pipes (LSU-atomic vs ALU/vote).
// ---------------------------------------------------------------------------
__global__ void __launch_bounds__(HIST_THREADS, 2) fused_kernel(
    const float4* __restrict__ feat_s, const float4* __restrict__ feat_t,
    float* __restrict__ out) {

    __shared__ unsigned int sh[NBINS][32];   // 32 KB, bank-exclusive columns

    #pragma unroll
    for (int i = threadIdx.x; i < NBINS * 32; i += HIST_THREADS)
        (&sh[0][0])[i] = 0u;
    __syncthreads();

    const float4* __restrict__ src = (blockIdx.z == 0) ? feat_s : feat_t;
    const int batch = blockIdx.y;
    const size_t base = (size_t)batch * F4_PER_BATCH
                      + (size_t)blockIdx.x * F4_PER_CHUNK;
    const int warp = threadIdx.x >> 5;
    const int lane = threadIdx.x & 31;

    const float4* gw = src + base + (size_t)warp * F4_PER_WARP;

    if (warp < ATOMIC_WARPS) {
        // ================= atomic path (ATOMS pipe) =================
        #pragma unroll 1
        for (int it = 0; it < WARP_ITERS; it += 8) {
            float4 v[8];
            #pragma unroll
            for (int k = 0; k < 8; k++)
                v[k] = __ldcs(&gw[(it + k) * 32 + lane]);
            #pragma unroll
            for (int k = 0; k < 8; k++) {
                atomicAdd(&sh[bin_of(v[k].x) & 0xFF][lane], 1u);
                atomicAdd(&sh[bin_of(v[k].y) & 0xFF][lane], 1u);
                atomicAdd(&sh[bin_of(v[k].z) & 0xFF][lane], 1u);
                atomicAdd(&sh[bin_of(v[k].w) & 0xFF][lane], 1u);
            }
        }
    } else {
        // ================= bit-slice path (ALU/vote pipes) =================
        // Lane L owns bins 8L..8L+7. High-bit match masks (bits 3..7 of bin
        // value == bits 0..4 of L): XOR constants per lane, hoisted.
        unsigned int x3 = (lane & 1)  ? 0u : ~0u;
        unsigned int x4 = (lane & 2)  ? 0u : ~0u;
        unsigned int x5 = (lane & 4)  ? 0u : ~0u;
        unsigned int x6 = (lane & 8)  ? 0u : ~0u;
        unsigned int x7 = (lane & 16) ? 0u : ~0u;
        unsigned int cnt[8] = {0,0,0,0,0,0,0,0};

        #pragma unroll 1
        for (int it = 0; it < WARP_ITERS; it++) {
            float4 v = __ldcs(&gw[it * 32 + lane]);
            float e4[4] = {v.x, v.y, v.z, v.w};
            #pragma unroll
            for (int c = 0; c < 4; c++) {
                unsigned int e = bin_of(e4[c]);   // low 8 bits = value
                unsigned int b0 = __ballot_sync(0xFFFFFFFFu, e & 1u);
                unsigned int b1 = __ballot_sync(0xFFFFFFFFu, e & 2u);
                unsigned int b2 = __ballot_sync(0xFFFFFFFFu, e & 4u);
                unsigned int b3 = __ballot_sync(0xFFFFFFFFu, e & 8u);
                unsigned int b4 = __ballot_sync(0xFFFFFFFFu, e & 16u);
                unsigned int b5 = __ballot_sync(0xFFFFFFFFu, e & 32u);
                unsigned int b6 = __ballot_sync(0xFFFFFFFFu, e & 64u);
                unsigned int b7 = __ballot_sync(0xFFFFFFFFu, e & 128u);
                unsigned int mhi = (b3 ^ x3) & (b4 ^ x4) & (b5 ^ x5)
                                 & (b6 ^ x6) & (b7 ^ x7);
                unsigned int n0 = ~b0, n1 = ~b1;
                unsigned int a00 = n1 & n0, a01 = n1 & b0;
                unsigned int a10 = b1 & n0, a11 = b1 & b0;
                unsigned int h0 = mhi & ~b2;     // bin bit2 = 0
                unsigned int h1 = mhi &  b2;     // bin bit2 = 1
                cnt[0] += __popc(h0 & a00);
                cnt[1] += __popc(h0 & a01);
                cnt[2] += __popc(h0 & a10);
                cnt[3] += __popc(h0 & a11);
                cnt[4] += __popc(h1 & a00);
                cnt[5] += __popc(h1 & a01);
                cnt[6] += __popc(h1 & a10);
                cnt[7] += __popc(h1 & a11);
            }
        }
        // merge register counters (bank-exclusive: bank == lane)
        #pragma unroll
        for (int j = 0; j < 8; j++)
            atomicAdd(&sh[(lane << 3) + j][lane], cnt[j]);
    }
    __syncthreads();

    // reduce 32 lane-columns per bin; rotated reads stay conflict-free
    if (threadIdx.x < NBINS) {
        const int b = threadIdx.x;
        unsigned int sum = 0;
        #pragma unroll
        for (int i = 0; i < 32; i++) sum += sh[b][(i + b) & 31];
        g_part[blockIdx.z][batch][blockIdx.x][b] = sum;
    }
    __syncthreads();

    // ---- per-batch ticket ----
    __shared__ unsigned int s_bticket;
    if (threadIdx.x == 0) {
        __threadfence();
        s_bticket = atomicAdd(&g_bctr[batch], 1u);
    }
    __syncthreads();
    if (s_bticket != BLOCKS_PER_BATCH - 1) return;

    // ======== this block is last for its batch: compute KL(batch) ========
    __threadfence();  // acquire: make all partials of this batch visible

    const int b = threadIdx.x;            // bin id for threads < NBINS
    __shared__ float rs[NBINS];
    __shared__ float rt[NBINS];

    float es = 0.f, et = 0.f, as_ = 0.f, at_ = 0.f;
    if (b < NBINS) {
        unsigned int cs = 0, ct = 0;
        #pragma unroll
        for (int c = 0; c < CHUNKS; c++) {
            cs += *((volatile unsigned int*)&g_part[0][batch][c][b]);
            ct += *((volatile unsigned int*)&g_part[1][batch][c][b]);
        }
        as_ = (float)cs + 1e-8f;
        at_ = (float)ct + 1e-8f;
        es = sqrtf(sqrtf(as_));           // (a)^(1/T), T = 4
        et = sqrtf(sqrtf(at_));
        rs[b] = es; rt[b] = et;
    }
    __syncthreads();
    #pragma unroll
    for (int s = NBINS / 2; s > 0; s >>= 1) {
        if (b < s) { rs[b] += rs[b + s]; rt[b] += rt[b + s]; }
        __syncthreads();
    }
    float Ss = rs[0];
    float St = rt[0];
    __syncthreads();

    if (b < NBINS) {
        float pt = et / St;                                   // softmax target
        float diff = 0.25f * logf(at_ / as_) - logf(St / Ss); // log p_t - log p_s
        rs[b] = pt * diff;
    }
    __syncthreads();
    #pragma unroll
    for (int s = NBINS / 2; s > 0; s >>= 1) {
        if (b < s) rs[b] += rs[b + s];
        __syncthreads();
    }

    // publish per-batch KL, reset batch ticket, take global ticket
    __shared__ unsigned int s_ticket;
    if (threadIdx.x == 0) {
        g_kl[batch] = rs[0];
        g_bctr[batch] = 0;                 // ready for next graph replay
        __threadfence();
        s_ticket = atomicAdd(&g_ctr, 1u);
    }
    __syncthreads();
    if (s_ticket != NBATCH - 1) return;

    // ======== very last batch-winner: deterministic final sum ========
    __threadfence();
    __shared__ float red[NBATCH];
    if (threadIdx.x < NBATCH) red[threadIdx.x] = *((volatile float*)&g_kl[threadIdx.x]);
    __syncthreads();
    #pragma unroll
    for (int s = NBATCH / 2; s > 0; s >>= 1) {
        if (threadIdx.x < s) red[threadIdx.x] += red[threadIdx.x + s];
        __syncthreads();
    }
    if (threadIdx.x == 0) {
        out[0] = red[0] * (16.0f / (float)NBATCH);  // * T^2 / N
        g_ctr = 0;                                  // ready for next replay
    }
}

// ---------------------------------------------------------------------------
extern "C" void kernel_launch(void* const* d_in, const int* in_sizes, int n_in,
                              void* d_out, int out_size) {
    const float4* feat_s = (const float4*)d_in[0];
    const float4* feat_t = (const float4*)d_in[1];
    float* out = (float*)d_out;

    (void)in_sizes; (void)n_in; (void)out_size;

    dim3 grid(CHUNKS, NBATCH, 2);
    fused_kernel<<<grid, HIST_THREADS>>>(feat_s, feat_t, out);
}